// round 8
// baseline (speedup 1.0000x reference)
#include <cuda_runtime.h>
#include <cstdint>

#define NCH         30
#define COORDW      5.0f
#define NOOBJW      0.5f
#define TPB         128
#define CELLS_PB    128
#define TILE_FLOATS (CELLS_PB * NCH)          // 3840 floats (data only)
#define TILE_BYTES  (TILE_FLOATS * 4)         // 15360 B
#define NSTAGE      2
#define SMEM_BYTES  (NSTAGE * TILE_BYTES)     // 30720 -> 6 blocks/SM with reserve
#define MAXGRID     2048

__device__ float        g_partials[MAXGRID];
__device__ unsigned int g_count = 0;

__device__ __forceinline__ uint32_t smem_u32(const void* p) {
    return (uint32_t)__cvta_generic_to_shared(p);
}
__device__ __forceinline__ void mbar_init(uint32_t mbar, uint32_t count) {
    asm volatile("mbarrier.init.shared.b64 [%0], %1;" :: "r"(mbar), "r"(count) : "memory");
}
__device__ __forceinline__ void mbar_expect_tx(uint32_t mbar, uint32_t bytes) {
    asm volatile("mbarrier.arrive.expect_tx.shared.b64 _, [%0], %1;"
                 :: "r"(mbar), "r"(bytes) : "memory");
}
__device__ __forceinline__ void mbar_wait(uint32_t mbar, uint32_t parity) {
    uint32_t done;
    asm volatile(
        "{\n\t"
        ".reg .pred p;\n\t"
        "mbarrier.try_wait.parity.acquire.cta.shared::cta.b64 p, [%1], %2;\n\t"
        "selp.b32 %0, 1, 0, p;\n\t"
        "}" : "=r"(done) : "r"(mbar), "r"(parity) : "memory");
    if (!done) {
        asm volatile(
            "{\n\t"
            ".reg .pred P1;\n\t"
            "WL_%=:\n\t"
            "mbarrier.try_wait.parity.acquire.cta.shared::cta.b64 P1, [%0], %1, 0x989680;\n\t"
            "@P1 bra.uni WD_%=;\n\t"
            "bra.uni WL_%=;\n\t"
            "WD_%=:\n\t"
            "}" :: "r"(mbar), "r"(parity) : "memory");
    }
}
__device__ __forceinline__ void bulk_g2s(uint32_t sdst, const void* gsrc,
                                         uint32_t bytes, uint32_t mbar) {
    asm volatile(
        "cp.async.bulk.shared::cta.global.mbarrier::complete_tx::bytes [%0], [%1], %2, [%3];"
        :: "r"(sdst), "l"(gsrc), "r"(bytes), "r"(mbar) : "memory");
}

__device__ __forceinline__ float warp_reduce(float v) {
    #pragma unroll
    for (int o = 16; o > 0; o >>= 1)
        v += __shfl_xor_sync(0xffffffffu, v, o);
    return v;
}

__device__ __forceinline__ void corners(float x, float y, float w, float h,
                                        float r, float c,
                                        float& x1, float& y1, float& x2, float& y2) {
    float cx = (x + c) * (1.0f / 7.0f);
    float cy = (y + r) * (1.0f / 7.0f);
    x1 = cx - w * 0.5f;
    y1 = cy - h * 0.5f;
    x2 = cx + w * 0.5f;
    y2 = cy + h * 0.5f;
}

__device__ __forceinline__ float iou(float ax1, float ay1, float ax2, float ay2,
                                     float bx1, float by1, float bx2, float by2) {
    float iw = fmaxf(fminf(ax2, bx2) - fmaxf(ax1, bx1), 0.0f);
    float ih = fmaxf(fminf(ay2, by2) - fmaxf(ay1, by1), 0.0f);
    float inter = iw * ih;
    float area_a = (ax2 - ax1) * (ay2 - ay1);
    float area_b = (bx2 - bx1) * (by2 - by1);
    float uni = area_a + area_b - inter;
    return (uni > 0.0f) ? __fdividef(inter, uni) : 0.0f;
}

// loss given label float2 registers + data float2 pointer (smem or gmem)
__device__ __forceinline__ float cell_loss_mixed(const float2* __restrict__ dp,
                                                 const float2 l01, const float2 l23,
                                                 const float2 l45, const float2 l67,
                                                 const float2 l89,
                                                 const float2* lcls,   // 10 float2 regs
                                                 float r, float c) {
    float2 d01 = dp[0], d23 = dp[1], d45 = dp[2], d67 = dp[3], d89 = dp[4];

    float b1x1, b1y1, b1x2, b1y2;
    float b2x1, b2y1, b2x2, b2y2;
    float gx1,  gy1,  gx2,  gy2;
    corners(d01.x, d01.y, d23.x, d23.y, r, c, b1x1, b1y1, b1x2, b1y2);
    corners(d45.y, d67.x, d67.y, d89.x, r, c, b2x1, b2y1, b2x2, b2y2);
    corners(l01.x, l01.y, l23.x, l23.y, r, c, gx1,  gy1,  gx2,  gy2);

    float iou1 = iou(b1x1, b1y1, b1x2, b1y2, gx1, gy1, gx2, gy2);
    float iou2 = iou(b2x1, b2y1, b2x2, b2y2, gx1, gy1, gx2, gy2);
    bool resp1 = (iou1 >= iou2);

    float dx1 = d01.x - l01.x, dy1 = d01.y - l01.y;
    float dx2 = d45.y - l45.y, dy2 = d67.x - l67.x;
    float xy1 = dx1 * dx1 + dy1 * dy1;
    float xy2 = dx2 * dx2 + dy2 * dy2;

    float sw1 = sqrtf(d23.x) - sqrtf(l23.x);
    float sh1 = sqrtf(d23.y) - sqrtf(l23.y);
    float sw2 = sqrtf(d67.y) - sqrtf(l67.y);
    float sh2 = sqrtf(d89.x) - sqrtf(l89.x);
    float wh1 = sw1 * sw1 + sh1 * sh1;
    float wh2 = sw2 * sw2 + sh2 * sh2;

    float d4 = d45.x, d9 = d89.y;

    float co    = COORDW * (resp1 ? xy1 : xy2);
    float wh    = COORDW * (resp1 ? wh1 : wh2);
    float cdiff = resp1 ? (d4 - iou1) : (d9 - iou2);
    float confi = cdiff * cdiff;
    float nin   = NOOBJW * (resp1 ? d9 * d9 : d4 * d4);

    float cls = 0.0f;
    #pragma unroll
    for (int i = 0; i < 10; i++) {
        float2 a = dp[5 + i], b = lcls[i];
        float ex = a.x - b.x;
        float ey = a.y - b.y;
        cls += ex * ex + ey * ey;
    }

    float m = (l45.x == 1.0f) ? 1.0f : 0.0f;
    float obj_loss   = m * (co + wh + confi + nin + cls);
    float noobj_loss = (1.0f - m) * NOOBJW * (d4 * d4 + d9 * d9);
    return obj_loss + noobj_loss;
}

__global__ void __launch_bounds__(TPB, 6)
yolo_loss_hybrid(const float* __restrict__ data,
                 const float* __restrict__ labels,
                 float* __restrict__ out,
                 int ncells, float invB, int ntiles) {
    extern __shared__ float smem[];                 // [NSTAGE][TILE_FLOATS] (data only)
    __shared__ __align__(8) uint64_t mbar_s[NSTAGE];
    __shared__ float sred[TPB / 32];
    __shared__ bool  s_last;

    const int tid = threadIdx.x;
    const int lane = tid & 31;
    const int warp = tid >> 5;
    const int gstride = gridDim.x;

    uint32_t mb[NSTAGE];
    #pragma unroll
    for (int s = 0; s < NSTAGE; s++) mb[s] = smem_u32(&mbar_s[s]);

    if (tid == 0) {
        #pragma unroll
        for (int s = 0; s < NSTAGE; s++) mbar_init(mb[s], 1);
    }
    __syncthreads();

    auto issue = [&](int tile, int s) {
        uint32_t dst = smem_u32(smem + s * TILE_FLOATS);
        mbar_expect_tx(mb[s], TILE_BYTES);
        bulk_g2s(dst, (const char*)data + (size_t)tile * TILE_BYTES, TILE_BYTES, mb[s]);
    };

    float acc = 0.0f;

    // prologue: depth-2 lookahead on the data stream
    if (tid == 0) {
        int t0 = blockIdx.x;
        if (t0 < ntiles && t0 * CELLS_PB + CELLS_PB <= ncells) issue(t0, 0);
        int t1 = t0 + gstride;
        if (t1 < ntiles && t1 * CELLS_PB + CELLS_PB <= ncells) issue(t1, 1);
    }

    int it = 0;
    for (int tile = blockIdx.x; tile < ntiles; tile += gstride, it++) {
        int cell = tile * CELLS_PB + tid;
        bool cur_full = (tile * CELLS_PB + CELLS_PB <= ncells);
        bool active = cell < ncells;
        int s = it & 1;
        uint32_t parity = (uint32_t)((it >> 1) & 1);

        // labels: 15 independent LDG.64 issued BEFORE the copy wait (latency overlap)
        float2 l01, l23, l45, l67, l89;
        float2 lcls[10];
        if (active) {
            const float2* lp = reinterpret_cast<const float2*>(labels) + (size_t)cell * 15;
            l01 = lp[0]; l23 = lp[1]; l45 = lp[2]; l67 = lp[3]; l89 = lp[4];
            #pragma unroll
            for (int i = 0; i < 10; i++) lcls[i] = lp[5 + i];
        }

        int within = cell % 49;
        float r = (float)(within / 7);
        float c = (float)(within % 7);

        if (cur_full) {
            mbar_wait(mb[s], parity);
            const float2* dp = reinterpret_cast<const float2*>(smem + s * TILE_FLOATS) + tid * 15;
            acc += cell_loss_mixed(dp, l01, l23, l45, l67, l89, lcls, r, c);
        } else if (active) {
            const float2* dp = reinterpret_cast<const float2*>(data) + (size_t)cell * 15;
            acc += cell_loss_mixed(dp, l01, l23, l45, l67, l89, lcls, r, c);
        }
        __syncthreads();     // everyone done with stage s

        int tnext = tile + 2 * gstride;
        if (tid == 0 && tnext < ntiles && tnext * CELLS_PB + CELLS_PB <= ncells)
            issue(tnext, s);
    }

    // deterministic block reduction
    float v = warp_reduce(acc);
    if (lane == 0) sred[warp] = v;
    __syncthreads();
    if (tid == 0) {
        float s = sred[0] + sred[1] + sred[2] + sred[3];
        g_partials[blockIdx.x] = s;
        __threadfence();
        unsigned int t = atomicAdd(&g_count, 1u);
        s_last = (t == (unsigned int)(gridDim.x - 1));
    }
    __syncthreads();

    if (s_last) {
        float s = 0.0f;
        for (int i = tid; i < (int)gridDim.x; i += TPB)
            s += g_partials[i];
        float w = warp_reduce(s);
        if (lane == 0) sred[warp] = w;
        __syncthreads();
        if (tid == 0) {
            float tot = sred[0] + sred[1] + sred[2] + sred[3];
            out[0] = tot * invB;
            g_count = 0;   // reset for next graph replay
        }
    }
}

extern "C" void kernel_launch(void* const* d_in, const int* in_sizes, int n_in,
                              void* d_out, int out_size) {
    const float* data   = (const float*)d_in[0];
    const float* labels = (const float*)d_in[1];
    float* out = (float*)d_out;

    int total  = in_sizes[0];           // B*7*7*30
    int ncells = total / NCH;           // B*49
    int B      = ncells / 49;

    int ntiles = (ncells + CELLS_PB - 1) / CELLS_PB;    // 3136 for B=8192
    int grid   = 888;                                    // 148 SM x 6 blocks (30.7KB smem each)
    if (grid > ntiles) grid = ntiles;
    if (grid > MAXGRID) grid = MAXGRID;

    cudaFuncSetAttribute(yolo_loss_hybrid,
                         cudaFuncAttributeMaxDynamicSharedMemorySize, SMEM_BYTES);

    yolo_loss_hybrid<<<grid, TPB, SMEM_BYTES>>>(data, labels, out,
                                                ncells, 1.0f / (float)B, ntiles);
}

// round 9
// speedup vs baseline: 1.2220x; 1.2220x over previous
#include <cuda_runtime.h>
#include <cstdint>

#define NCH         30
#define COORDW      5.0f
#define NOOBJW      0.5f
#define TPB         128
#define CELLS_PB    128
#define TILE_FLOATS (CELLS_PB * NCH)          // 3840 floats per array
#define TILE_BYTES  (TILE_FLOATS * 4)         // 15360 B per array
#define STAGE_FLOATS (2 * TILE_FLOATS)        // data + labels
#define STAGE_BYTES  (STAGE_FLOATS * 4)       // 30720 B
#define NSTAGE      3
#define SMEM_BYTES  (NSTAGE * STAGE_BYTES)    // 92160 -> 2 blocks/SM
#define MAXGRID     1024

__device__ float        g_partials[MAXGRID];
__device__ unsigned int g_count = 0;

__device__ __forceinline__ uint32_t smem_u32(const void* p) {
    return (uint32_t)__cvta_generic_to_shared(p);
}
__device__ __forceinline__ void mbar_init(uint32_t mbar, uint32_t count) {
    asm volatile("mbarrier.init.shared.b64 [%0], %1;" :: "r"(mbar), "r"(count) : "memory");
}
__device__ __forceinline__ void mbar_expect_tx(uint32_t mbar, uint32_t bytes) {
    asm volatile("mbarrier.arrive.expect_tx.shared.b64 _, [%0], %1;"
                 :: "r"(mbar), "r"(bytes) : "memory");
}
__device__ __forceinline__ void mbar_wait(uint32_t mbar, uint32_t parity) {
    uint32_t done;
    asm volatile(
        "{\n\t"
        ".reg .pred p;\n\t"
        "mbarrier.try_wait.parity.acquire.cta.shared::cta.b64 p, [%1], %2;\n\t"
        "selp.b32 %0, 1, 0, p;\n\t"
        "}" : "=r"(done) : "r"(mbar), "r"(parity) : "memory");
    if (!done) {
        asm volatile(
            "{\n\t"
            ".reg .pred P1;\n\t"
            "WL_%=:\n\t"
            "mbarrier.try_wait.parity.acquire.cta.shared::cta.b64 P1, [%0], %1, 0x989680;\n\t"
            "@P1 bra.uni WD_%=;\n\t"
            "bra.uni WL_%=;\n\t"
            "WD_%=:\n\t"
            "}" :: "r"(mbar), "r"(parity) : "memory");
    }
}
__device__ __forceinline__ void bulk_g2s(uint32_t sdst, const void* gsrc,
                                         uint32_t bytes, uint32_t mbar) {
    asm volatile(
        "cp.async.bulk.shared::cta.global.mbarrier::complete_tx::bytes [%0], [%1], %2, [%3];"
        :: "r"(sdst), "l"(gsrc), "r"(bytes), "r"(mbar) : "memory");
}

__device__ __forceinline__ float warp_reduce(float v) {
    #pragma unroll
    for (int o = 16; o > 0; o >>= 1)
        v += __shfl_xor_sync(0xffffffffu, v, o);
    return v;
}

__device__ __forceinline__ void corners(float x, float y, float w, float h,
                                        float r, float c,
                                        float& x1, float& y1, float& x2, float& y2) {
    float cx = (x + c) * (1.0f / 7.0f);
    float cy = (y + r) * (1.0f / 7.0f);
    x1 = cx - w * 0.5f;
    y1 = cy - h * 0.5f;
    x2 = cx + w * 0.5f;
    y2 = cy + h * 0.5f;
}

__device__ __forceinline__ float iou(float ax1, float ay1, float ax2, float ay2,
                                     float bx1, float by1, float bx2, float by2) {
    float iw = fmaxf(fminf(ax2, bx2) - fmaxf(ax1, bx1), 0.0f);
    float ih = fmaxf(fminf(ay2, by2) - fmaxf(ay1, by1), 0.0f);
    float inter = iw * ih;
    float area_a = (ax2 - ax1) * (ay2 - ay1);
    float area_b = (bx2 - bx1) * (by2 - by1);
    float uni = area_a + area_b - inter;
    return (uni > 0.0f) ? __fdividef(inter, uni) : 0.0f;
}

__device__ __forceinline__ float cell_loss2(const float2* __restrict__ dp,
                                            const float2* __restrict__ lp,
                                            float r, float c) {
    float2 d01 = dp[0], d23 = dp[1], d45 = dp[2], d67 = dp[3], d89 = dp[4];
    float2 l01 = lp[0], l23 = lp[1], l45 = lp[2], l67 = lp[3], l89 = lp[4];

    float b1x1, b1y1, b1x2, b1y2;
    float b2x1, b2y1, b2x2, b2y2;
    float gx1,  gy1,  gx2,  gy2;
    corners(d01.x, d01.y, d23.x, d23.y, r, c, b1x1, b1y1, b1x2, b1y2);
    corners(d45.y, d67.x, d67.y, d89.x, r, c, b2x1, b2y1, b2x2, b2y2);
    corners(l01.x, l01.y, l23.x, l23.y, r, c, gx1,  gy1,  gx2,  gy2);

    float iou1 = iou(b1x1, b1y1, b1x2, b1y2, gx1, gy1, gx2, gy2);
    float iou2 = iou(b2x1, b2y1, b2x2, b2y2, gx1, gy1, gx2, gy2);
    bool resp1 = (iou1 >= iou2);

    float dx1 = d01.x - l01.x, dy1 = d01.y - l01.y;
    float dx2 = d45.y - l45.y, dy2 = d67.x - l67.x;
    float xy1 = dx1 * dx1 + dy1 * dy1;
    float xy2 = dx2 * dx2 + dy2 * dy2;

    float sw1 = sqrtf(d23.x) - sqrtf(l23.x);
    float sh1 = sqrtf(d23.y) - sqrtf(l23.y);
    float sw2 = sqrtf(d67.y) - sqrtf(l67.y);
    float sh2 = sqrtf(d89.x) - sqrtf(l89.x);
    float wh1 = sw1 * sw1 + sh1 * sh1;
    float wh2 = sw2 * sw2 + sh2 * sh2;

    float d4 = d45.x, d9 = d89.y;

    float co    = COORDW * (resp1 ? xy1 : xy2);
    float wh    = COORDW * (resp1 ? wh1 : wh2);
    float cdiff = resp1 ? (d4 - iou1) : (d9 - iou2);
    float confi = cdiff * cdiff;
    float nin   = NOOBJW * (resp1 ? d9 * d9 : d4 * d4);

    float cls = 0.0f;
    #pragma unroll
    for (int i = 5; i < 15; i++) {
        float2 a = dp[i], b = lp[i];
        float ex = a.x - b.x;
        float ey = a.y - b.y;
        cls += ex * ex + ey * ey;
    }

    float m = (l45.x == 1.0f) ? 1.0f : 0.0f;
    float obj_loss   = m * (co + wh + confi + nin + cls);
    float noobj_loss = (1.0f - m) * NOOBJW * (d4 * d4 + d9 * d9);
    return obj_loss + noobj_loss;
}

__global__ void __launch_bounds__(TPB, 2)
yolo_loss_bal(const float* __restrict__ data,
              const float* __restrict__ labels,
              float* __restrict__ out,
              int ncells, float invB) {
    extern __shared__ float smem[];                 // [NSTAGE][STAGE_FLOATS]
    __shared__ __align__(8) uint64_t mbar_s[NSTAGE];
    __shared__ float sred[TPB / 32];
    __shared__ bool  s_last;

    const int tid = threadIdx.x;
    const int lane = tid & 31;
    const int warp = tid >> 5;
    const int bid = blockIdx.x;
    const int grid = gridDim.x;

    // contiguous near-equal range per block, in 2-cell units (16B-aligned TMA)
    const long long half = (long long)(ncells >> 1);
    const int start_cell = (int)(2 * ((half * bid) / grid));
    const int end_cell   = (int)(2 * ((half * (bid + 1)) / grid));
    const int nchunks = (end_cell - start_cell + CELLS_PB - 1) / CELLS_PB;

    uint32_t mb[NSTAGE];
    #pragma unroll
    for (int s = 0; s < NSTAGE; s++) mb[s] = smem_u32(&mbar_s[s]);

    if (tid == 0) {
        #pragma unroll
        for (int s = 0; s < NSTAGE; s++) mbar_init(mb[s], 1);
    }
    __syncthreads();

    // issue chunk k's copies into stage s (tid 0 only; caller guards k < nchunks)
    auto issue = [&](int k, int s) {
        int cs = start_cell + k * CELLS_PB;
        int chunk = min(CELLS_PB, end_cell - cs);       // even, >0
        uint32_t bytes = (uint32_t)chunk * (NCH * 4);
        uint32_t dst = smem_u32(smem + s * STAGE_FLOATS);
        mbar_expect_tx(mb[s], 2 * bytes);
        bulk_g2s(dst,              (const char*)data   + (size_t)cs * (NCH * 4), bytes, mb[s]);
        bulk_g2s(dst + TILE_BYTES, (const char*)labels + (size_t)cs * (NCH * 4), bytes, mb[s]);
    };

    if (tid == 0) {
        if (nchunks > 0) issue(0, 0);
        if (nchunks > 1) issue(1, 1);
    }

    float acc = 0.0f;

    for (int k = 0; k < nchunks; k++) {
        int s = k % NSTAGE;
        uint32_t parity = (uint32_t)((k / NSTAGE) & 1);
        int cs = start_cell + k * CELLS_PB;
        int chunk = min(CELLS_PB, end_cell - cs);

        mbar_wait(mb[s], parity);

        if (tid < chunk) {
            const float* sd = smem + s * STAGE_FLOATS;
            const float* sl = sd + TILE_FLOATS;
            int cell = cs + tid;
            int within = cell % 49;
            float r = (float)(within / 7);
            float c = (float)(within % 7);
            acc += cell_loss2(reinterpret_cast<const float2*>(sd) + tid * 15,
                              reinterpret_cast<const float2*>(sl) + tid * 15,
                              r, c);
        }
        __syncthreads();     // all threads done with stage s

        int knext = k + 2;
        if (tid == 0 && knext < nchunks)
            issue(knext, (knext) % NSTAGE);
    }

    // odd leftover cell (ncells odd): last block, thread 0, direct loads
    if (bid == grid - 1 && tid == 0 && (ncells & 1)) {
        int cell = ncells - 1;
        int within = cell % 49;
        float r = (float)(within / 7);
        float c = (float)(within % 7);
        acc += cell_loss2(reinterpret_cast<const float2*>(data)   + (size_t)cell * 15,
                          reinterpret_cast<const float2*>(labels) + (size_t)cell * 15,
                          r, c);
    }

    // deterministic block reduction
    float v = warp_reduce(acc);
    if (lane == 0) sred[warp] = v;
    __syncthreads();
    if (tid == 0) {
        float s = sred[0] + sred[1] + sred[2] + sred[3];
        g_partials[bid] = s;
        __threadfence();
        unsigned int t = atomicAdd(&g_count, 1u);
        s_last = (t == (unsigned int)(grid - 1));
    }
    __syncthreads();

    if (s_last) {
        float s = 0.0f;
        for (int i = tid; i < grid; i += TPB)
            s += g_partials[i];
        float w = warp_reduce(s);
        if (lane == 0) sred[warp] = w;
        __syncthreads();
        if (tid == 0) {
            float tot = sred[0] + sred[1] + sred[2] + sred[3];
            out[0] = tot * invB;
            g_count = 0;   // reset for next graph replay
        }
    }
}

extern "C" void kernel_launch(void* const* d_in, const int* in_sizes, int n_in,
                              void* d_out, int out_size) {
    const float* data   = (const float*)d_in[0];
    const float* labels = (const float*)d_in[1];
    float* out = (float*)d_out;

    int total  = in_sizes[0];           // B*7*7*30
    int ncells = total / NCH;           // B*49
    int B      = ncells / 49;

    int grid = 296;                     // 148 SM x 2 blocks (92KB smem each), 1 wave
    if (grid > MAXGRID) grid = MAXGRID;
    int half = ncells >> 1;
    if (half > 0 && grid > half) grid = half;
    if (grid < 1) grid = 1;

    cudaFuncSetAttribute(yolo_loss_bal,
                         cudaFuncAttributeMaxDynamicSharedMemorySize, SMEM_BYTES);

    yolo_loss_bal<<<grid, TPB, SMEM_BYTES>>>(data, labels, out,
                                             ncells, 1.0f / (float)B);
}

// round 10
// speedup vs baseline: 1.2405x; 1.0152x over previous
#include <cuda_runtime.h>
#include <cstdint>

#define NCH          30
#define COORDW       5.0f
#define NOOBJW       0.5f
#define TPB          128
#define CELLS_PC     96                          // cells per chunk (= 3 consumer warps)
#define CHUNK_FLOATS (CELLS_PC * NCH)            // 2880 floats per array
#define CHUNK_BYTES  (CHUNK_FLOATS * 4)          // 11520 B per array
#define STAGE_FLOATS (2 * CHUNK_FLOATS)          // data + labels = 5760
#define STAGE_BYTES  (STAGE_FLOATS * 4)          // 23040 B
#define NSTAGE       4
#define SMEM_BYTES   (NSTAGE * STAGE_BYTES)      // 92160 -> 2 blocks/SM
#define MAXGRID      1024

__device__ float        g_partials[MAXGRID];
__device__ unsigned int g_count = 0;

__device__ __forceinline__ uint32_t smem_u32(const void* p) {
    return (uint32_t)__cvta_generic_to_shared(p);
}
__device__ __forceinline__ void mbar_init(uint32_t mbar, uint32_t count) {
    asm volatile("mbarrier.init.shared.b64 [%0], %1;" :: "r"(mbar), "r"(count) : "memory");
}
__device__ __forceinline__ void mbar_expect_tx(uint32_t mbar, uint32_t bytes) {
    asm volatile("mbarrier.arrive.expect_tx.shared.b64 _, [%0], %1;"
                 :: "r"(mbar), "r"(bytes) : "memory");
}
__device__ __forceinline__ void mbar_arrive(uint32_t mbar) {
    asm volatile("mbarrier.arrive.shared.b64 _, [%0];" :: "r"(mbar) : "memory");
}
__device__ __forceinline__ void mbar_wait(uint32_t mbar, uint32_t parity) {
    uint32_t done;
    asm volatile(
        "{\n\t"
        ".reg .pred p;\n\t"
        "mbarrier.try_wait.parity.acquire.cta.shared::cta.b64 p, [%1], %2;\n\t"
        "selp.b32 %0, 1, 0, p;\n\t"
        "}" : "=r"(done) : "r"(mbar), "r"(parity) : "memory");
    if (!done) {
        asm volatile(
            "{\n\t"
            ".reg .pred P1;\n\t"
            "WL_%=:\n\t"
            "mbarrier.try_wait.parity.acquire.cta.shared::cta.b64 P1, [%0], %1, 0x989680;\n\t"
            "@P1 bra.uni WD_%=;\n\t"
            "bra.uni WL_%=;\n\t"
            "WD_%=:\n\t"
            "}" :: "r"(mbar), "r"(parity) : "memory");
    }
}
__device__ __forceinline__ void bulk_g2s(uint32_t sdst, const void* gsrc,
                                         uint32_t bytes, uint32_t mbar) {
    asm volatile(
        "cp.async.bulk.shared::cta.global.mbarrier::complete_tx::bytes [%0], [%1], %2, [%3];"
        :: "r"(sdst), "l"(gsrc), "r"(bytes), "r"(mbar) : "memory");
}

__device__ __forceinline__ float warp_reduce(float v) {
    #pragma unroll
    for (int o = 16; o > 0; o >>= 1)
        v += __shfl_xor_sync(0xffffffffu, v, o);
    return v;
}

__device__ __forceinline__ void corners(float x, float y, float w, float h,
                                        float r, float c,
                                        float& x1, float& y1, float& x2, float& y2) {
    float cx = (x + c) * (1.0f / 7.0f);
    float cy = (y + r) * (1.0f / 7.0f);
    x1 = cx - w * 0.5f;
    y1 = cy - h * 0.5f;
    x2 = cx + w * 0.5f;
    y2 = cy + h * 0.5f;
}

__device__ __forceinline__ float iou(float ax1, float ay1, float ax2, float ay2,
                                     float bx1, float by1, float bx2, float by2) {
    float iw = fmaxf(fminf(ax2, bx2) - fmaxf(ax1, bx1), 0.0f);
    float ih = fmaxf(fminf(ay2, by2) - fmaxf(ay1, by1), 0.0f);
    float inter = iw * ih;
    float area_a = (ax2 - ax1) * (ay2 - ay1);
    float area_b = (bx2 - bx1) * (by2 - by1);
    float uni = area_a + area_b - inter;
    return (uni > 0.0f) ? __fdividef(inter, uni) : 0.0f;
}

__device__ __forceinline__ float cell_loss2(const float2* __restrict__ dp,
                                            const float2* __restrict__ lp,
                                            float r, float c) {
    float2 d01 = dp[0], d23 = dp[1], d45 = dp[2], d67 = dp[3], d89 = dp[4];
    float2 l01 = lp[0], l23 = lp[1], l45 = lp[2], l67 = lp[3], l89 = lp[4];

    float b1x1, b1y1, b1x2, b1y2;
    float b2x1, b2y1, b2x2, b2y2;
    float gx1,  gy1,  gx2,  gy2;
    corners(d01.x, d01.y, d23.x, d23.y, r, c, b1x1, b1y1, b1x2, b1y2);
    corners(d45.y, d67.x, d67.y, d89.x, r, c, b2x1, b2y1, b2x2, b2y2);
    corners(l01.x, l01.y, l23.x, l23.y, r, c, gx1,  gy1,  gx2,  gy2);

    float iou1 = iou(b1x1, b1y1, b1x2, b1y2, gx1, gy1, gx2, gy2);
    float iou2 = iou(b2x1, b2y1, b2x2, b2y2, gx1, gy1, gx2, gy2);
    bool resp1 = (iou1 >= iou2);

    float dx1 = d01.x - l01.x, dy1 = d01.y - l01.y;
    float dx2 = d45.y - l45.y, dy2 = d67.x - l67.x;
    float xy1 = dx1 * dx1 + dy1 * dy1;
    float xy2 = dx2 * dx2 + dy2 * dy2;

    float sw1 = sqrtf(d23.x) - sqrtf(l23.x);
    float sh1 = sqrtf(d23.y) - sqrtf(l23.y);
    float sw2 = sqrtf(d67.y) - sqrtf(l67.y);
    float sh2 = sqrtf(d89.x) - sqrtf(l89.x);
    float wh1 = sw1 * sw1 + sh1 * sh1;
    float wh2 = sw2 * sw2 + sh2 * sh2;

    float d4 = d45.x, d9 = d89.y;

    float co    = COORDW * (resp1 ? xy1 : xy2);
    float wh    = COORDW * (resp1 ? wh1 : wh2);
    float cdiff = resp1 ? (d4 - iou1) : (d9 - iou2);
    float confi = cdiff * cdiff;
    float nin   = NOOBJW * (resp1 ? d9 * d9 : d4 * d4);

    float cls = 0.0f;
    #pragma unroll
    for (int i = 5; i < 15; i++) {
        float2 a = dp[i], b = lp[i];
        float ex = a.x - b.x;
        float ey = a.y - b.y;
        cls += ex * ex + ey * ey;
    }

    float m = (l45.x == 1.0f) ? 1.0f : 0.0f;
    float obj_loss   = m * (co + wh + confi + nin + cls);
    float noobj_loss = (1.0f - m) * NOOBJW * (d4 * d4 + d9 * d9);
    return obj_loss + noobj_loss;
}

__global__ void __launch_bounds__(TPB, 2)
yolo_loss_ws(const float* __restrict__ data,
             const float* __restrict__ labels,
             float* __restrict__ out,
             int ncells, float invB, int nchunks) {
    extern __shared__ float smem[];                       // [NSTAGE][STAGE_FLOATS]
    __shared__ __align__(8) uint64_t full_s[NSTAGE];
    __shared__ __align__(8) uint64_t empty_s[NSTAGE];
    __shared__ float sred[TPB / 32];
    __shared__ bool  s_last;

    const int tid  = threadIdx.x;
    const int lane = tid & 31;
    const int warp = tid >> 5;
    const int bid  = blockIdx.x;
    const int grid = gridDim.x;

    uint32_t fullb[NSTAGE], emptyb[NSTAGE];
    #pragma unroll
    for (int s = 0; s < NSTAGE; s++) {
        fullb[s]  = smem_u32(&full_s[s]);
        emptyb[s] = smem_u32(&empty_s[s]);
    }

    if (tid == 0) {
        #pragma unroll
        for (int s = 0; s < NSTAGE; s++) {
            mbar_init(fullb[s], 1);     // producer's expect_tx arrive
            mbar_init(emptyb[s], 3);    // one arrive per consumer warp
        }
    }
    __syncthreads();

    float acc = 0.0f;

    if (warp == 3) {
        // ── producer: lane 0 drives the ring as fast as empties appear ──
        if (lane == 0) {
            int k = 0;
            for (int chunk = bid; chunk < nchunks; chunk += grid, k++) {
                int s = k & (NSTAGE - 1);
                uint32_t p_empty = 1u ^ ((uint32_t)(k >> 2) & 1u);  // first wrap passes
                mbar_wait(emptyb[s], p_empty);

                int cs = chunk * CELLS_PC;
                int cells = min(CELLS_PC, ncells - cs);              // even (96 or 32)
                uint32_t bytes = (uint32_t)cells * (NCH * 4);
                uint32_t dst = smem_u32(smem + s * STAGE_FLOATS);
                mbar_expect_tx(fullb[s], 2 * bytes);
                bulk_g2s(dst,                (const char*)data   + (size_t)cs * (NCH * 4), bytes, fullb[s]);
                bulk_g2s(dst + CHUNK_BYTES,  (const char*)labels + (size_t)cs * (NCH * 4), bytes, fullb[s]);
            }
        }
    } else {
        // ── consumers: warps 0-2, tid 0..95 ↔ cell within chunk ──
        int k = 0;
        for (int chunk = bid; chunk < nchunks; chunk += grid, k++) {
            int s = k & (NSTAGE - 1);
            uint32_t p_full = (uint32_t)(k >> 2) & 1u;
            mbar_wait(fullb[s], p_full);

            int cs = chunk * CELLS_PC;
            int cells = min(CELLS_PC, ncells - cs);
            if (tid < cells) {
                const float* sd = smem + s * STAGE_FLOATS;
                const float* sl = sd + CHUNK_FLOATS;
                int cell = cs + tid;
                int within = cell % 49;
                float r = (float)(within / 7);
                float c = (float)(within % 7);
                acc += cell_loss2(reinterpret_cast<const float2*>(sd) + tid * 15,
                                  reinterpret_cast<const float2*>(sl) + tid * 15,
                                  r, c);
            }
            __syncwarp();
            if (lane == 0) mbar_arrive(emptyb[s]);   // release stage s
        }
    }

    // ── deterministic block reduction (all 4 warps) ──
    float v = warp_reduce(acc);
    if (lane == 0) sred[warp] = v;
    __syncthreads();
    if (tid == 0) {
        float s = sred[0] + sred[1] + sred[2] + sred[3];
        g_partials[bid] = s;
        __threadfence();
        unsigned int t = atomicAdd(&g_count, 1u);
        s_last = (t == (unsigned int)(grid - 1));
    }
    __syncthreads();

    if (s_last) {
        float s = 0.0f;
        for (int i = tid; i < grid; i += TPB)
            s += g_partials[i];
        float w = warp_reduce(s);
        if (lane == 0) sred[warp] = w;
        __syncthreads();
        if (tid == 0) {
            float tot = sred[0] + sred[1] + sred[2] + sred[3];
            out[0] = tot * invB;
            g_count = 0;   // reset for next graph replay
        }
    }
}

extern "C" void kernel_launch(void* const* d_in, const int* in_sizes, int n_in,
                              void* d_out, int out_size) {
    const float* data   = (const float*)d_in[0];
    const float* labels = (const float*)d_in[1];
    float* out = (float*)d_out;

    int total  = in_sizes[0];           // B*7*7*30
    int ncells = total / NCH;           // B*49
    int B      = ncells / 49;

    int nchunks = (ncells + CELLS_PC - 1) / CELLS_PC;   // 4182 for B=8192
    int grid = 296;                                      // 148 SM x 2 blocks (92KB smem)
    if (grid > nchunks) grid = nchunks;
    if (grid > MAXGRID) grid = MAXGRID;

    cudaFuncSetAttribute(yolo_loss_ws,
                         cudaFuncAttributeMaxDynamicSharedMemorySize, SMEM_BYTES);

    yolo_loss_ws<<<grid, TPB, SMEM_BYTES>>>(data, labels, out,
                                            ncells, 1.0f / (float)B, nchunks);
}

// round 11
// speedup vs baseline: 1.2452x; 1.0038x over previous
#include <cuda_runtime.h>
#include <cstdint>

#define NCH          30
#define COORDW       5.0f
#define NOOBJW       0.5f
#define TPB          256
#define CELLS_PC     256                         // cells per chunk = TPB
#define CHUNK_FLOATS (CELLS_PC * NCH)            // 7680 floats per array
#define CHUNK_BYTES  (CHUNK_FLOATS * 4)          // 30720 B per array
#define STAGE_FLOATS (2 * CHUNK_FLOATS)          // data + labels = 15360
#define STAGE_BYTES  (STAGE_FLOATS * 4)          // 61440 B
#define NSTAGE       3
#define SMEM_BYTES   (NSTAGE * STAGE_BYTES)      // 184320 -> 1 block/SM
#define MAXGRID      1024

__device__ float        g_partials[MAXGRID];
__device__ unsigned int g_count = 0;

__device__ __forceinline__ uint32_t smem_u32(const void* p) {
    return (uint32_t)__cvta_generic_to_shared(p);
}
__device__ __forceinline__ void mbar_init(uint32_t mbar, uint32_t count) {
    asm volatile("mbarrier.init.shared.b64 [%0], %1;" :: "r"(mbar), "r"(count) : "memory");
}
__device__ __forceinline__ void mbar_expect_tx(uint32_t mbar, uint32_t bytes) {
    asm volatile("mbarrier.arrive.expect_tx.shared.b64 _, [%0], %1;"
                 :: "r"(mbar), "r"(bytes) : "memory");
}
__device__ __forceinline__ void mbar_wait(uint32_t mbar, uint32_t parity) {
    uint32_t done;
    asm volatile(
        "{\n\t"
        ".reg .pred p;\n\t"
        "mbarrier.try_wait.parity.acquire.cta.shared::cta.b64 p, [%1], %2;\n\t"
        "selp.b32 %0, 1, 0, p;\n\t"
        "}" : "=r"(done) : "r"(mbar), "r"(parity) : "memory");
    if (!done) {
        asm volatile(
            "{\n\t"
            ".reg .pred P1;\n\t"
            "WL_%=:\n\t"
            "mbarrier.try_wait.parity.acquire.cta.shared::cta.b64 P1, [%0], %1, 0x989680;\n\t"
            "@P1 bra.uni WD_%=;\n\t"
            "bra.uni WL_%=;\n\t"
            "WD_%=:\n\t"
            "}" :: "r"(mbar), "r"(parity) : "memory");
    }
}
__device__ __forceinline__ void bulk_g2s(uint32_t sdst, const void* gsrc,
                                         uint32_t bytes, uint32_t mbar) {
    asm volatile(
        "cp.async.bulk.shared::cta.global.mbarrier::complete_tx::bytes [%0], [%1], %2, [%3];"
        :: "r"(sdst), "l"(gsrc), "r"(bytes), "r"(mbar) : "memory");
}

__device__ __forceinline__ float warp_reduce(float v) {
    #pragma unroll
    for (int o = 16; o > 0; o >>= 1)
        v += __shfl_xor_sync(0xffffffffu, v, o);
    return v;
}

__device__ __forceinline__ void corners(float x, float y, float w, float h,
                                        float r, float c,
                                        float& x1, float& y1, float& x2, float& y2) {
    float cx = (x + c) * (1.0f / 7.0f);
    float cy = (y + r) * (1.0f / 7.0f);
    x1 = cx - w * 0.5f;
    y1 = cy - h * 0.5f;
    x2 = cx + w * 0.5f;
    y2 = cy + h * 0.5f;
}

__device__ __forceinline__ float iou(float ax1, float ay1, float ax2, float ay2,
                                     float bx1, float by1, float bx2, float by2) {
    float iw = fmaxf(fminf(ax2, bx2) - fmaxf(ax1, bx1), 0.0f);
    float ih = fmaxf(fminf(ay2, by2) - fmaxf(ay1, by1), 0.0f);
    float inter = iw * ih;
    float area_a = (ax2 - ax1) * (ay2 - ay1);
    float area_b = (bx2 - bx1) * (by2 - by1);
    float uni = area_a + area_b - inter;
    return (uni > 0.0f) ? __fdividef(inter, uni) : 0.0f;
}

__device__ __forceinline__ float cell_loss2(const float2* __restrict__ dp,
                                            const float2* __restrict__ lp,
                                            float r, float c) {
    float2 d01 = dp[0], d23 = dp[1], d45 = dp[2], d67 = dp[3], d89 = dp[4];
    float2 l01 = lp[0], l23 = lp[1], l45 = lp[2], l67 = lp[3], l89 = lp[4];

    float b1x1, b1y1, b1x2, b1y2;
    float b2x1, b2y1, b2x2, b2y2;
    float gx1,  gy1,  gx2,  gy2;
    corners(d01.x, d01.y, d23.x, d23.y, r, c, b1x1, b1y1, b1x2, b1y2);
    corners(d45.y, d67.x, d67.y, d89.x, r, c, b2x1, b2y1, b2x2, b2y2);
    corners(l01.x, l01.y, l23.x, l23.y, r, c, gx1,  gy1,  gx2,  gy2);

    float iou1 = iou(b1x1, b1y1, b1x2, b1y2, gx1, gy1, gx2, gy2);
    float iou2 = iou(b2x1, b2y1, b2x2, b2y2, gx1, gy1, gx2, gy2);
    bool resp1 = (iou1 >= iou2);

    float dx1 = d01.x - l01.x, dy1 = d01.y - l01.y;
    float dx2 = d45.y - l45.y, dy2 = d67.x - l67.x;
    float xy1 = dx1 * dx1 + dy1 * dy1;
    float xy2 = dx2 * dx2 + dy2 * dy2;

    float sw1 = sqrtf(d23.x) - sqrtf(l23.x);
    float sh1 = sqrtf(d23.y) - sqrtf(l23.y);
    float sw2 = sqrtf(d67.y) - sqrtf(l67.y);
    float sh2 = sqrtf(d89.x) - sqrtf(l89.x);
    float wh1 = sw1 * sw1 + sh1 * sh1;
    float wh2 = sw2 * sw2 + sh2 * sh2;

    float d4 = d45.x, d9 = d89.y;

    float co    = COORDW * (resp1 ? xy1 : xy2);
    float wh    = COORDW * (resp1 ? wh1 : wh2);
    float cdiff = resp1 ? (d4 - iou1) : (d9 - iou2);
    float confi = cdiff * cdiff;
    float nin   = NOOBJW * (resp1 ? d9 * d9 : d4 * d4);

    float cls = 0.0f;
    #pragma unroll
    for (int i = 5; i < 15; i++) {
        float2 a = dp[i], b = lp[i];
        float ex = a.x - b.x;
        float ey = a.y - b.y;
        cls += ex * ex + ey * ey;
    }

    float m = (l45.x == 1.0f) ? 1.0f : 0.0f;
    float obj_loss   = m * (co + wh + confi + nin + cls);
    float noobj_loss = (1.0f - m) * NOOBJW * (d4 * d4 + d9 * d9);
    return obj_loss + noobj_loss;
}

__global__ void __launch_bounds__(TPB, 1)
yolo_loss_big(const float* __restrict__ data,
              const float* __restrict__ labels,
              float* __restrict__ out,
              int ncells, float invB, int nchunks) {
    extern __shared__ float smem[];                 // [NSTAGE][STAGE_FLOATS]
    __shared__ __align__(8) uint64_t mbar_s[NSTAGE];
    __shared__ float sred[TPB / 32];
    __shared__ bool  s_last;

    const int tid = threadIdx.x;
    const int lane = tid & 31;
    const int warp = tid >> 5;
    const int bid = blockIdx.x;
    const int grid = gridDim.x;

    uint32_t mb[NSTAGE];
    #pragma unroll
    for (int s = 0; s < NSTAGE; s++) mb[s] = smem_u32(&mbar_s[s]);

    if (tid == 0) {
        #pragma unroll
        for (int s = 0; s < NSTAGE; s++) mbar_init(mb[s], 1);
    }
    __syncthreads();

    // issue chunk's copies into stage s (even cell count via TMA; odd cell handled separately)
    auto issue = [&](int chunk, int s) {
        int cs = chunk * CELLS_PC;
        int cells = min(CELLS_PC, ncells - cs) & ~1;    // even part
        if (cells <= 0) { mbar_expect_tx(mb[s], 0); return; }
        uint32_t bytes = (uint32_t)cells * (NCH * 4);
        uint32_t dst = smem_u32(smem + s * STAGE_FLOATS);
        mbar_expect_tx(mb[s], 2 * bytes);
        bulk_g2s(dst,               (const char*)data   + (size_t)cs * (NCH * 4), bytes, mb[s]);
        bulk_g2s(dst + CHUNK_BYTES, (const char*)labels + (size_t)cs * (NCH * 4), bytes, mb[s]);
    };

    if (tid == 0) {
        if (bid < nchunks)        issue(bid, 0);
        if (bid + grid < nchunks) issue(bid + grid, 1);
    }

    float acc = 0.0f;

    int k = 0;
    for (int chunk = bid; chunk < nchunks; chunk += grid, k++) {
        int s = k % NSTAGE;
        uint32_t parity = (uint32_t)((k / NSTAGE) & 1);
        int cs = chunk * CELLS_PC;
        int cells_even = min(CELLS_PC, ncells - cs) & ~1;

        mbar_wait(mb[s], parity);

        if (tid < cells_even) {
            const float* sd = smem + s * STAGE_FLOATS;
            const float* sl = sd + CHUNK_FLOATS;
            int cell = cs + tid;
            int within = cell % 49;
            float r = (float)(within / 7);
            float c = (float)(within % 7);
            acc += cell_loss2(reinterpret_cast<const float2*>(sd) + tid * 15,
                              reinterpret_cast<const float2*>(sl) + tid * 15,
                              r, c);
        }
        __syncthreads();     // all threads done with stage s

        int cnext = chunk + 2 * grid;
        if (tid == 0 && cnext < nchunks)
            issue(cnext, (k + 2) % NSTAGE);
    }

    // odd leftover cell (ncells odd): handled once, directly
    if ((ncells & 1) && bid == ((ncells / CELLS_PC) % grid) && tid == 0) {
        int cell = ncells - 1;
        int within = cell % 49;
        float r = (float)(within / 7);
        float c = (float)(within % 7);
        acc += cell_loss2(reinterpret_cast<const float2*>(data)   + (size_t)cell * 15,
                          reinterpret_cast<const float2*>(labels) + (size_t)cell * 15,
                          r, c);
    }

    // deterministic block reduction (8 warps)
    float v = warp_reduce(acc);
    if (lane == 0) sred[warp] = v;
    __syncthreads();
    if (tid == 0) {
        float s = 0.0f;
        #pragma unroll
        for (int i = 0; i < TPB / 32; i++) s += sred[i];
        g_partials[bid] = s;
        __threadfence();
        unsigned int t = atomicAdd(&g_count, 1u);
        s_last = (t == (unsigned int)(grid - 1));
    }
    __syncthreads();

    if (s_last) {
        float s = 0.0f;
        for (int i = tid; i < grid; i += TPB)
            s += g_partials[i];
        float w = warp_reduce(s);
        if (lane == 0) sred[warp] = w;
        __syncthreads();
        if (tid == 0) {
            float tot = 0.0f;
            #pragma unroll
            for (int i = 0; i < TPB / 32; i++) tot += sred[i];
            out[0] = tot * invB;
            g_count = 0;   // reset for next graph replay
        }
    }
}

extern "C" void kernel_launch(void* const* d_in, const int* in_sizes, int n_in,
                              void* d_out, int out_size) {
    const float* data   = (const float*)d_in[0];
    const float* labels = (const float*)d_in[1];
    float* out = (float*)d_out;

    int total  = in_sizes[0];           // B*7*7*30
    int ncells = total / NCH;           // B*49
    int B      = ncells / 49;

    int nchunks = (ncells + CELLS_PC - 1) / CELLS_PC;   // 1568 for B=8192
    int grid = 148;                                      // 1 block/SM, 184KB smem
    if (grid > nchunks) grid = nchunks;
    if (grid > MAXGRID) grid = MAXGRID;
    if (grid < 1) grid = 1;

    cudaFuncSetAttribute(yolo_loss_big,
                         cudaFuncAttributeMaxDynamicSharedMemorySize, SMEM_BYTES);

    yolo_loss_big<<<grid, TPB, SMEM_BYTES>>>(data, labels, out,
                                             ncells, 1.0f / (float)B, nchunks);
}